// round 10
// baseline (speedup 1.0000x reference)
#include <cuda_runtime.h>
#include <cstdint>

#define ROWS   4096
#define FDIM   16384
#define BINS   128
#define NFEAT  257
#define OUT    64
#define HB     512
#define NW     (HB / 32)      // 16 warps
#define NCOPY  8              // histogram copies (warp pairs)

// Precomputed by wave-1 CTAs during their TMA-wait window
__device__ __align__(16) float g_WTc[BINS * OUT];   // counts-part W, transposed [i][j]
__device__ __align__(16) float g_u[OUT];            // sum_k W[j][128+k]
__device__ __align__(16) float g_v[OUT];            // sum_k (k/128) W[j][128+k]

__device__ __forceinline__ uint32_t smem_u32(const void* p) {
    uint32_t a;
    asm("{ .reg .u64 t; cvta.to.shared.u64 t, %1; cvt.u32.u64 %0, t; }" : "=r"(a) : "l"(p));
    return a;
}

// ---------------------------------------------------------------------------
// Fused single kernel.
// Dynamic smem: [0, 64K) row | [64K, 64K+4.5K) aux:
//   phase A: hist = u32[NCOPY*BINS] (4 KB)
//   phase B: s_cnt = f32[128], spart = float4[256]  (4.5 KB)
// ---------------------------------------------------------------------------
__global__ __launch_bounds__(HB, 3) void fused_kernel(const float* __restrict__ x,
                                                      const float* __restrict__ W,
                                                      const float* __restrict__ bias,
                                                      float* __restrict__ out) {
    extern __shared__ __align__(16) float sdata[];             // row: 16384 floats
    float* aux = sdata + FDIM;
    unsigned int* hist = reinterpret_cast<unsigned int*>(aux);

    __shared__ float s_red[2 * NW];
    __shared__ float s_mnw[2];
    __shared__ float s_uv[2 * 4];          // (u,v) warp partials for W-prep
    __shared__ __align__(8) unsigned long long mbar;

    const int row  = blockIdx.x;
    const int tid  = threadIdx.x;
    const int warp = tid >> 5;
    const int lane = tid & 31;

    // zero histogram copies
    #pragma unroll
    for (int k = 0; k < (NCOPY * BINS) / HB; k++)
        hist[tid + k * HB] = 0u;

    const uint32_t mbar_a = smem_u32(&mbar);
    const uint32_t data_a = smem_u32(sdata);

    if (tid == 0) {
        asm volatile("mbarrier.init.shared.b64 [%0], 1;" :: "r"(mbar_a) : "memory");
        asm volatile("fence.proxy.async.shared::cta;" ::: "memory");
    }
    __syncthreads();

    if (tid == 0) {
        asm volatile("mbarrier.arrive.expect_tx.shared.b64 _, [%0], %1;"
                     :: "r"(mbar_a), "r"(FDIM * 4) : "memory");
        const float* src = x + (size_t)row * FDIM;
        asm volatile("cp.async.bulk.shared::cta.global.mbarrier::complete_tx::bytes "
                     "[%0], [%1], %2, [%3];"
                     :: "r"(data_a), "l"(src), "r"(FDIM * 4), "r"(mbar_a) : "memory");
    }

    // ---- one-time W prep, overlapped with the in-flight TMA (wave-1 blocks) ----
    if (row < OUT) {
        // transpose counts-part: g_WTc[i][row] = W[row][i]
        if (tid < BINS) g_WTc[tid * OUT + row] = W[row * NFEAT + tid];
    } else if (row < 2 * OUT) {
        // fold boundary-part into (u, v), deterministic reduction order
        const int j = row - OUT;
        float u = 0.0f, v = 0.0f;
        if (warp < 4) {
            int k = warp * 32 + lane;              // 0..127
            float w = W[j * NFEAT + BINS + k];
            u = w;
            v = (float)k * (1.0f / 128.0f) * w;
            #pragma unroll
            for (int o = 16; o > 0; o >>= 1) {
                u += __shfl_xor_sync(0xffffffffu, u, o);
                v += __shfl_xor_sync(0xffffffffu, v, o);
            }
            if (lane == 0) { s_uv[warp] = u; s_uv[4 + warp] = v; }
        }
        __syncthreads();
        if (tid == 0) {
            float wlast = W[j * NFEAT + BINS + 128];   // k = 128 term
            g_u[j] = ((s_uv[0] + s_uv[1]) + (s_uv[2] + s_uv[3])) + wlast;
            g_v[j] = ((s_uv[4] + s_uv[5]) + (s_uv[6] + s_uv[7])) + wlast; // t=1
        }
    }

    // ---- wait for TMA (parity 0) ----
    {
        uint32_t done;
        asm volatile("{\n\t.reg .pred p;\n\t"
                     "mbarrier.try_wait.parity.acquire.cta.shared::cta.b64 p, [%1], 0;\n\t"
                     "selp.b32 %0, 1, 0, p;\n\t}"
                     : "=r"(done) : "r"(mbar_a) : "memory");
        while (!done) {
            asm volatile("{\n\t.reg .pred p;\n\t"
                         "mbarrier.try_wait.parity.acquire.cta.shared::cta.b64 p, [%1], 0, 0x989680;\n\t"
                         "selp.b32 %0, 1, 0, p;\n\t}"
                         : "=r"(done) : "r"(mbar_a) : "memory");
        }
    }

    const float4* sd4 = reinterpret_cast<const float4*>(sdata);

    // pass 1: min/max (8 x float4 per thread)
    float mn, mx;
    {
        float4 v0 = sd4[tid];
        mn = fminf(fminf(v0.x, v0.y), fminf(v0.z, v0.w));
        mx = fmaxf(fmaxf(v0.x, v0.y), fmaxf(v0.z, v0.w));
        #pragma unroll
        for (int k = 1; k < 8; k++) {
            float4 v = sd4[tid + k * HB];
            mn = fminf(mn, fminf(fminf(v.x, v.y), fminf(v.z, v.w)));
            mx = fmaxf(mx, fmaxf(fmaxf(v.x, v.y), fmaxf(v.z, v.w)));
        }
    }
    #pragma unroll
    for (int o = 16; o > 0; o >>= 1) {
        mn = fminf(mn, __shfl_xor_sync(0xffffffffu, mn, o));
        mx = fmaxf(mx, __shfl_xor_sync(0xffffffffu, mx, o));
    }
    if (lane == 0) { s_red[warp] = mn; s_red[NW + warp] = mx; }
    __syncthreads();
    if (tid == 0) {
        float m = s_red[0], M = s_red[NW];
        #pragma unroll
        for (int i = 1; i < NW; i++) {
            m = fminf(m, s_red[i]);
            M = fmaxf(M, s_red[NW + i]);
        }
        s_mnw[0] = m;
        s_mnw[1] = M - m;
    }
    __syncthreads();

    const float row_mn = s_mnw[0];
    const float width  = s_mnw[1];
    const float invw   = 128.0f / ((width == 0.0f) ? 1.0f : width);
    const float nmn    = -row_mn * invw;

    uint32_t lml;
    asm("mov.u32 %0, %%lanemask_lt;" : "=r"(lml));

    // pass 2: binning with warp-aggregated atomics.
    // v >= mn => fma >= -1ulp, so int-trunc == floor + lower clamp.
    unsigned int* h = &hist[(warp >> 1) * BINS];
    #pragma unroll
    for (int k = 0; k < 8; k++) {
        float4 v = sd4[tid + k * HB];
        float vals[4] = {v.x, v.y, v.z, v.w};
        #pragma unroll
        for (int e = 0; e < 4; e++) {
            int b = (int)__fmaf_rn(vals[e], invw, nmn);
            b = min(b, BINS - 1);
            unsigned m = __match_any_sync(0xffffffffu, b);
            if ((m & lml) == 0)                      // lowest lane in group
                atomicAdd(&h[b], __popc(m));
        }
    }
    __syncthreads();

    // reduce copies into registers, then alias aux region
    unsigned int cnt = 0;
    if (tid < BINS) {
        #pragma unroll
        for (int c = 0; c < NCOPY; c++) cnt += hist[c * BINS + tid];
    }
    __syncthreads();                                  // hist dead

    float*  s_cnt = aux;                              // [128]
    float4* spart = reinterpret_cast<float4*>(aux + BINS);  // [16][16]

    if (tid < BINS) s_cnt[tid] = (float)cnt;
    __syncthreads();

    // dot: thread = (j4 = tid&15, p = tid>>4); p covers 4 bins
    const int j4 = tid & 15;
    const int p  = tid >> 4;
    const float4* WTc4 = reinterpret_cast<const float4*>(g_WTc);

    float4 acc = make_float4(0.f, 0.f, 0.f, 0.f);
    #pragma unroll
    for (int k = 0; k < 4; k++) {
        int i = p * 4 + k;                            // 0..127
        float  fv = s_cnt[i];
        float4 wv = WTc4[i * (OUT / 4) + j4];
        acc.x += fv * wv.x;
        acc.y += fv * wv.y;
        acc.z += fv * wv.z;
        acc.w += fv * wv.w;
    }
    acc.x += __shfl_xor_sync(0xffffffffu, acc.x, 16);
    acc.y += __shfl_xor_sync(0xffffffffu, acc.y, 16);
    acc.z += __shfl_xor_sync(0xffffffffu, acc.z, 16);
    acc.w += __shfl_xor_sync(0xffffffffu, acc.w, 16);
    if (lane < 16) spart[warp * 16 + lane] = acc;
    __syncthreads();

    if (tid < OUT) {
        const float* sp = reinterpret_cast<const float*>(spart);  // [16][64]
        float s = 0.0f;
        #pragma unroll
        for (int w = 0; w < NW; w++) s += sp[w * OUT + tid];
        float o = s * (1.0f / 16384.0f)
                + row_mn * g_u[tid] + width * g_v[tid] + bias[tid];
        out[(size_t)row * OUT + tid] = o;
    }
}

// ---------------------------------------------------------------------------
extern "C" void kernel_launch(void* const* d_in, const int* in_sizes, int n_in,
                              void* d_out, int out_size) {
    const float* x    = (const float*)d_in[0];   // [4096, 16384]
    const float* W    = (const float*)d_in[1];   // [64, 257]
    const float* bias = (const float*)d_in[2];   // [64]
    float* out = (float*)d_out;                  // [4096, 64]

    // 64 KB row + 4.5 KB aux = 70144 B -> 3 CTAs/SM after granularity rounding
    const int dyn_smem = FDIM * 4 + (BINS + 4 * 256) * 4;
    cudaFuncSetAttribute(fused_kernel, cudaFuncAttributeMaxDynamicSharedMemorySize, dyn_smem);

    fused_kernel<<<ROWS, HB, dyn_smem>>>(x, W, bias, out);
}

// round 11
// speedup vs baseline: 6.4521x; 6.4521x over previous
#include <cuda_runtime.h>
#include <cstdint>

#define ROWS   4096
#define FDIM   16384
#define BINS   128
#define NFEAT  257
#define OUT    64
#define HB     512
#define NW     (HB / 32)      // 16 warps
#define NCOPY  16             // per-warp histogram copies (proven config)

// Written by wave-1 CTAs during their TMA-wait window, read by all epilogues
__device__ __align__(16) float g_WTc[BINS * OUT];   // counts-part W, transposed [i][j]
__device__ __align__(16) float g_u[OUT];            // sum_k W[j][128+k]
__device__ __align__(16) float g_v[OUT];            // sum_k (k/128) W[j][128+k]

__device__ __forceinline__ uint32_t smem_u32(const void* p) {
    uint32_t a;
    asm("{ .reg .u64 t; cvta.to.shared.u64 t, %1; cvt.u32.u64 %0, t; }" : "=r"(a) : "l"(p));
    return a;
}

// ---------------------------------------------------------------------------
// Single fused kernel.
// Dynamic smem: [0, 64K) row | [64K, 72K) aux:
//   phase A: hist = u32[16*128]  (8 KB)
//   phase B: s_cnt = f32[128], spart = float4[16*16]  (4.6 KB, aliased)
// ---------------------------------------------------------------------------
__global__ __launch_bounds__(HB, 3) void fused_kernel(const float* __restrict__ x,
                                                      const float* __restrict__ W,
                                                      const float* __restrict__ bias,
                                                      float* __restrict__ out) {
    extern __shared__ __align__(16) float sdata[];             // row: 16384 floats
    float* aux = sdata + FDIM;
    unsigned int* hist = reinterpret_cast<unsigned int*>(aux);

    __shared__ float s_red[2 * NW];
    __shared__ float s_mnw[2];
    __shared__ __align__(8) unsigned long long mbar;

    const int row  = blockIdx.x;
    const int tid  = threadIdx.x;
    const int warp = tid >> 5;
    const int lane = tid & 31;

    // zero per-warp histogram copies (16*128 u32 = 8 KB)
    #pragma unroll
    for (int k = 0; k < (NCOPY * BINS) / HB; k++)
        hist[tid + k * HB] = 0u;

    const uint32_t mbar_a = smem_u32(&mbar);
    const uint32_t data_a = smem_u32(sdata);

    if (tid == 0) {
        asm volatile("mbarrier.init.shared.b64 [%0], 1;" :: "r"(mbar_a) : "memory");
        asm volatile("fence.proxy.async.shared::cta;" ::: "memory");
    }
    __syncthreads();

    if (tid == 0) {
        asm volatile("mbarrier.arrive.expect_tx.shared.b64 _, [%0], %1;"
                     :: "r"(mbar_a), "r"(FDIM * 4) : "memory");
        const float* src = x + (size_t)row * FDIM;
        asm volatile("cp.async.bulk.shared::cta.global.mbarrier::complete_tx::bytes "
                     "[%0], [%1], %2, [%3];"
                     :: "r"(data_a), "l"(src), "r"(FDIM * 4), "r"(mbar_a) : "memory");
    }

    // ---- one-time W prep, overlapped with the in-flight TMA (wave-1 CTAs) ----
    if (row < OUT) {
        // transpose counts-part: g_WTc[i][row] = W[row][i]
        if (tid < BINS) g_WTc[tid * OUT + row] = W[row * NFEAT + tid];
        if (tid == 0) __threadfence();
    } else if (row < 2 * OUT) {
        // fold boundary-part into (u, v) with a single warp; no block sync needed
        const int j = row - OUT;
        if (warp == 0) {
            const float* wb = W + j * NFEAT + BINS;      // W[j][128..256]
            float u = 0.0f, v = 0.0f;
            #pragma unroll
            for (int q = 0; q < 4; q++) {
                int k = q * 32 + lane;                   // 0..127
                float w = wb[k];
                u += w;
                v += (float)k * (1.0f / 128.0f) * w;
            }
            if (lane == 0) { u += wb[128]; v += wb[128]; }   // k=128 term, t=1
            #pragma unroll
            for (int o = 16; o > 0; o >>= 1) {
                u += __shfl_xor_sync(0xffffffffu, u, o);
                v += __shfl_xor_sync(0xffffffffu, v, o);
            }
            if (lane == 0) {
                g_u[j] = u;
                g_v[j] = v;
                __threadfence();
            }
        }
    }

    // ---- wait for TMA (parity 0) ----
    {
        uint32_t done;
        asm volatile("{\n\t.reg .pred p;\n\t"
                     "mbarrier.try_wait.parity.acquire.cta.shared::cta.b64 p, [%1], 0;\n\t"
                     "selp.b32 %0, 1, 0, p;\n\t}"
                     : "=r"(done) : "r"(mbar_a) : "memory");
        while (!done) {
            asm volatile("{\n\t.reg .pred p;\n\t"
                         "mbarrier.try_wait.parity.acquire.cta.shared::cta.b64 p, [%1], 0, 0x989680;\n\t"
                         "selp.b32 %0, 1, 0, p;\n\t}"
                         : "=r"(done) : "r"(mbar_a) : "memory");
        }
    }

    const float4* sd4 = reinterpret_cast<const float4*>(sdata);

    // pass 1: min/max (8 x float4 per thread)
    float mn, mx;
    {
        float4 v0 = sd4[tid];
        mn = fminf(fminf(v0.x, v0.y), fminf(v0.z, v0.w));
        mx = fmaxf(fmaxf(v0.x, v0.y), fmaxf(v0.z, v0.w));
        #pragma unroll
        for (int k = 1; k < 8; k++) {
            float4 v = sd4[tid + k * HB];
            mn = fminf(mn, fminf(fminf(v.x, v.y), fminf(v.z, v.w)));
            mx = fmaxf(mx, fmaxf(fmaxf(v.x, v.y), fmaxf(v.z, v.w)));
        }
    }
    #pragma unroll
    for (int o = 16; o > 0; o >>= 1) {
        mn = fminf(mn, __shfl_xor_sync(0xffffffffu, mn, o));
        mx = fmaxf(mx, __shfl_xor_sync(0xffffffffu, mx, o));
    }
    if (lane == 0) { s_red[warp] = mn; s_red[NW + warp] = mx; }
    __syncthreads();
    if (tid == 0) {
        float m = s_red[0], M = s_red[NW];
        #pragma unroll
        for (int i = 1; i < NW; i++) {
            m = fminf(m, s_red[i]);
            M = fmaxf(M, s_red[NW + i]);
        }
        s_mnw[0] = m;
        s_mnw[1] = M - m;
    }
    __syncthreads();

    const float row_mn = s_mnw[0];
    const float width  = s_mnw[1];
    const float invw   = 128.0f / ((width == 0.0f) ? 1.0f : width);
    const float nmn    = -row_mn * invw;

    // pass 2: binning into this warp's private copy (plain atomics — proven).
    // v >= mn => fma >= -1ulp, so int-trunc == floor + lower clamp.
    unsigned int* h = &hist[warp * BINS];
    #pragma unroll
    for (int k = 0; k < 8; k++) {
        float4 v = sd4[tid + k * HB];
        float vals[4] = {v.x, v.y, v.z, v.w};
        #pragma unroll
        for (int e = 0; e < 4; e++) {
            int b = (int)__fmaf_rn(vals[e], invw, nmn);
            b = min(b, BINS - 1);
            atomicAdd(&h[b], 1u);
        }
    }
    __syncthreads();

    // reduce the 16 copies into registers, then alias the aux region
    unsigned int cnt = 0;
    if (tid < BINS) {
        #pragma unroll
        for (int c = 0; c < NCOPY; c++) cnt += hist[c * BINS + tid];
    }
    __syncthreads();                                  // hist dead

    float*  s_cnt = aux;                              // [128]
    float4* spart = reinterpret_cast<float4*>(aux + BINS);  // [16][16]

    if (tid < BINS) s_cnt[tid] = (float)cnt;
    __syncthreads();

    // epilogue dot: thread = (j4 = tid&15, p = tid>>4); p covers 4 bins
    const int j4 = tid & 15;
    const int p  = tid >> 4;
    const float4* WTc4 = reinterpret_cast<const float4*>(g_WTc);

    float4 acc = make_float4(0.f, 0.f, 0.f, 0.f);
    #pragma unroll
    for (int k = 0; k < 4; k++) {
        int i = p * 4 + k;                            // 0..127
        float  fv = s_cnt[i];
        float4 wv = WTc4[i * (OUT / 4) + j4];
        acc.x += fv * wv.x;
        acc.y += fv * wv.y;
        acc.z += fv * wv.z;
        acc.w += fv * wv.w;
    }
    acc.x += __shfl_xor_sync(0xffffffffu, acc.x, 16);
    acc.y += __shfl_xor_sync(0xffffffffu, acc.y, 16);
    acc.z += __shfl_xor_sync(0xffffffffu, acc.z, 16);
    acc.w += __shfl_xor_sync(0xffffffffu, acc.w, 16);
    if (lane < 16) spart[warp * 16 + lane] = acc;
    __syncthreads();

    if (tid < OUT) {
        const float* sp = reinterpret_cast<const float*>(spart);  // [16][64]
        float s = 0.0f;
        #pragma unroll
        for (int w = 0; w < NW; w++) s += sp[w * OUT + tid];
        float o = s * (1.0f / 16384.0f)
                + row_mn * g_u[tid] + width * g_v[tid] + bias[tid];
        out[(size_t)row * OUT + tid] = o;
    }
}

// ---------------------------------------------------------------------------
extern "C" void kernel_launch(void* const* d_in, const int* in_sizes, int n_in,
                              void* d_out, int out_size) {
    const float* x    = (const float*)d_in[0];   // [4096, 16384]
    const float* W    = (const float*)d_in[1];   // [64, 257]
    const float* bias = (const float*)d_in[2];   // [64]
    float* out = (float*)d_out;                  // [4096, 64]

    const int dyn_smem = (FDIM + NCOPY * BINS) * 4;   // 64 KB row + 8 KB aux
    cudaFuncSetAttribute(fused_kernel, cudaFuncAttributeMaxDynamicSharedMemorySize, dyn_smem);

    fused_kernel<<<ROWS, HB, dyn_smem>>>(x, W, bias, out);
}